// round 1
// baseline (speedup 1.0000x reference)
#include <cuda_runtime.h>
#include <cuda_bf16.h>
#include <math.h>

// HungarianMatcher cost matrix:
//   C[n, t] = 5*L1(mid_n, mid_t) + 2*(pos_cost - neg_cost)[n, label_t]
//           + 5*(L1(head_n, head_t) + L1(tip_n, tip_t))
// n over bs*nq = 28800, t over 960 targets, nc = 2.
// Output is reshape([bs,nq,T]) of [N,T] row-major -> flat [N,T].
//
// Strategy: precompute per-query focal class costs (both classes) + midpoints,
// and per-target label+coords+midpoints, into __device__ scratch. Main kernel
// is pure fixed-latency FP with coalesced STG.128 -> HBM-write-bound.

#define COST_CLASS 2.0f
#define COST_MID 5.0f
#define COST_HT 5.0f
#define EPS_F 1e-8f

#define MAX_N 65536
#define MAX_T 4096
#define QT 8        // queries per block in main kernel

__device__ float g_q[MAX_N * 8];   // {cls0, cls1, hx, hy, tx, ty, mx, my}
__device__ float g_t[MAX_T * 8];   // {lbl(bits), thx, thy, ttx, tty, tmx, tmy, pad}

__global__ void prep_queries(const float* __restrict__ logits,
                             const float* __restrict__ screws,
                             int N, int nc) {
    int i = blockIdx.x * blockDim.x + threadIdx.x;
    if (i >= N) return;

    float l0 = logits[(long long)i * nc + 0];
    float l1 = (nc > 1) ? logits[(long long)i * nc + 1] : l0;

    float p0 = 1.0f / (1.0f + expf(-l0));
    float p1 = 1.0f / (1.0f + expf(-l1));

    // pos = (1-p)^2 * -log(p + eps); neg = p^2 * -log1p(-(p - eps))
    float pos0 = (1.0f - p0) * (1.0f - p0) * (-logf(p0 + EPS_F));
    float neg0 = p0 * p0 * (-log1pf(-(p0 - EPS_F)));
    float pos1 = (1.0f - p1) * (1.0f - p1) * (-logf(p1 + EPS_F));
    float neg1 = p1 * p1 * (-log1pf(-(p1 - EPS_F)));

    float4 s = reinterpret_cast<const float4*>(screws)[i];

    float4 a, b;
    a.x = COST_CLASS * (pos0 - neg0);
    a.y = COST_CLASS * (pos1 - neg1);
    a.z = s.x;            // head x
    a.w = s.y;            // head y
    b.x = s.z;            // tip x
    b.y = s.w;            // tip y
    b.z = (s.x + s.z) * 0.5f;  // mid x
    b.w = (s.y + s.w) * 0.5f;  // mid y

    reinterpret_cast<float4*>(g_q)[i * 2 + 0] = a;
    reinterpret_cast<float4*>(g_q)[i * 2 + 1] = b;
}

__global__ void prep_targets(const int* __restrict__ labels,
                             const float* __restrict__ screws,
                             int T) {
    int i = blockIdx.x * blockDim.x + threadIdx.x;
    if (i >= T) return;

    float4 s = reinterpret_cast<const float4*>(screws)[i];
    float4 a, b;
    a.x = __int_as_float(labels[i]);
    a.y = s.x;                  // head x
    a.z = s.y;                  // head y
    a.w = s.z;                  // tip x
    b.x = s.w;                  // tip y
    b.y = (s.x + s.z) * 0.5f;   // mid x
    b.z = (s.y + s.w) * 0.5f;   // mid y
    b.w = 0.0f;

    reinterpret_cast<float4*>(g_t)[i * 2 + 0] = a;
    reinterpret_cast<float4*>(g_t)[i * 2 + 1] = b;
}

__global__ __launch_bounds__(256)
void cost_main(float* __restrict__ out, int N, int T) {
    // Each thread owns 4 consecutive targets; block covers QT queries.
    int t0 = threadIdx.x * 4;
    if (t0 >= T) return;
    int qbase = blockIdx.x * QT;
    bool full4 = (t0 + 3) < T;

    // Load 4 targets into registers once.
    int   lbl[4];
    float thx[4], thy[4], ttx[4], tty[4], tmx[4], tmy[4];
    int nt = full4 ? 4 : (T - t0);
    #pragma unroll
    for (int j = 0; j < 4; j++) {
        int tj = (j < nt) ? (t0 + j) : t0;
        float4 a = reinterpret_cast<const float4*>(g_t)[tj * 2 + 0];
        float4 b = reinterpret_cast<const float4*>(g_t)[tj * 2 + 1];
        lbl[j] = __float_as_int(a.x);
        thx[j] = a.y; thy[j] = a.z; ttx[j] = a.w;
        tty[j] = b.x; tmx[j] = b.y; tmy[j] = b.z;
    }

    #pragma unroll
    for (int q = 0; q < QT; q++) {
        int qi = qbase + q;
        if (qi >= N) return;

        float4 qa = reinterpret_cast<const float4*>(g_q)[qi * 2 + 0];
        float4 qb = reinterpret_cast<const float4*>(g_q)[qi * 2 + 1];
        float cls0 = qa.x, cls1 = qa.y;
        float hx = qa.z, hy = qa.w, tx = qb.x, ty = qb.y, mx = qb.z, my = qb.w;

        float r[4];
        #pragma unroll
        for (int j = 0; j < 4; j++) {
            float s = fabsf(mx - tmx[j]) + fabsf(my - tmy[j])
                    + fabsf(hx - thx[j]) + fabsf(hy - thy[j])
                    + fabsf(tx - ttx[j]) + fabsf(ty - tty[j]);
            float cls = (lbl[j] == 0) ? cls0 : cls1;
            r[j] = fmaf(COST_MID, s, cls);   // COST_MID == COST_HT == 5
        }

        long long base = (long long)qi * T + t0;
        if (full4) {
            float4 v; v.x = r[0]; v.y = r[1]; v.z = r[2]; v.w = r[3];
            *reinterpret_cast<float4*>(out + base) = v;
        } else {
            for (int j = 0; j < nt; j++) out[base + j] = r[j];
        }
    }
}

extern "C" void kernel_launch(void* const* d_in, const int* in_sizes, int n_in,
                              void* d_out, int out_size) {
    const float* logits   = (const float*)d_in[0];   // [bs, nq, nc]
    const float* pscrews  = (const float*)d_in[1];   // [bs, nq, 4]
    const int*   tlabels  = (const int*)d_in[2];     // [T]
    const float* tscrews  = (const float*)d_in[3];   // [T, 4]
    // d_in[4] = num_targets_per_image: only used by the reference to shape
    // targets; the flat [N, T] output does not depend on it.

    int N  = in_sizes[1] / 4;          // bs * nq
    int nc = in_sizes[0] / N;          // 2
    int T  = in_sizes[2];              // total targets
    float* out = (float*)d_out;

    {
        int tpb = 256;
        prep_queries<<<(N + tpb - 1) / tpb, tpb>>>(logits, pscrews, N, nc);
        prep_targets<<<(T + tpb - 1) / tpb, tpb>>>(tlabels, tscrews, T);
    }

    // 256 threads cover up to 1024 targets (4 per thread). T=960 -> 240 active.
    int blocks = (N + QT - 1) / QT;
    cost_main<<<blocks, 256>>>(out, N, T);
}

// round 2
// speedup vs baseline: 1.7392x; 1.7392x over previous
#include <cuda_runtime.h>
#include <cuda_bf16.h>
#include <math.h>

// HungarianMatcher cost matrix, fully fused single kernel.
//   C[n, t] = 5*(|mid_n-mid_t| + |head_n-head_t| + |tip_n-tip_t|)_L1
//           + 2*(pos-neg)[n, label_t]
// n over N = bs*nq (28800), t over T (960) targets, nc = 2.
//
// Geometric part uses Blackwell packed f32x2 (FADD2/FFMA2 via PTX) on (x,y)
// pairs: 3 packed subs + abs(and.b64 -> alu pipe) + 2 packed adds + 2 FFMA-imm.
// Class costs are computed once per block (blocks partition queries) into smem.
// Output is streamed with __stcs (write-once, > L2).

#define QT 8          // queries per block
#define TPT 4         // targets per thread
#define MAXNC 16

typedef unsigned long long u64;

__device__ __forceinline__ u64 pk2(float lo, float hi) {
    u64 r; asm("mov.b64 %0, {%1, %2};" : "=l"(r) : "f"(lo), "f"(hi)); return r;
}
__device__ __forceinline__ void upk2(u64 v, float& lo, float& hi) {
    asm("mov.b64 {%0, %1}, %2;" : "=f"(lo), "=f"(hi) : "l"(v));
}
__device__ __forceinline__ u64 addx2(u64 a, u64 b) {
    u64 r; asm("add.rn.f32x2 %0, %1, %2;" : "=l"(r) : "l"(a), "l"(b)); return r;
}
__device__ __forceinline__ u64 mulx2(u64 a, u64 b) {
    u64 r; asm("mul.rn.f32x2 %0, %1, %2;" : "=l"(r) : "l"(a), "l"(b)); return r;
}
__device__ __forceinline__ u64 absx2(u64 a) {
    u64 r; asm("and.b64 %0, %1, 0x7FFFFFFF7FFFFFFF;" : "=l"(r) : "l"(a)); return r;
}

__global__ __launch_bounds__(256)
void matcher_fused(const float* __restrict__ logits,
                   const float* __restrict__ pscrews,
                   const int*   __restrict__ tlabels,
                   const float* __restrict__ tscrews,
                   float* __restrict__ out,
                   int N, int nc, int T) {
    __shared__ float s_cls[QT * MAXNC];

    int qbase = blockIdx.x * QT;

    // ---- per-block focal class costs (blocks partition queries: no redundancy)
    int k = threadIdx.x;
    if (k < QT * nc) {
        int q = qbase + k / nc;
        int c = k % nc;
        float cost = 0.0f;
        if (q < N) {
            float l = logits[(long long)q * nc + c];
            float p = 1.0f / (1.0f + expf(-l));
            float pos = (1.0f - p) * (1.0f - p) * (-logf(p + 1e-8f));
            float neg = p * p * (-log1pf(-(p - 1e-8f)));
            cost = 2.0f * (pos - neg);
        }
        s_cls[k] = cost;
    }
    __syncthreads();

    // ---- load TPT targets into registers (negated, so inner loop is pure adds)
    const u64 NEG1 = 0xBF800000BF800000ULL;  // {-1, -1}
    const u64 NEGH = 0xBF000000BF000000ULL;  // {-0.5, -0.5}
    const u64 HALF = 0x3F0000003F000000ULL;  // {0.5, 0.5}

    int t0 = threadIdx.x * TPT;
    bool active = (t0 < T);
    int nt = active ? min(TPT, T - t0) : 0;
    bool full = (nt == TPT);

    u64 ntm[TPT], nth[TPT], ntt[TPT];
    int lofs[TPT];
    if (active) {
        #pragma unroll
        for (int j = 0; j < TPT; j++) {
            int tj = t0 + ((j < nt) ? j : (nt - 1));
            float4 s = reinterpret_cast<const float4*>(tscrews)[tj];
            u64 h2 = pk2(s.x, s.y);
            u64 t2 = pk2(s.z, s.w);
            nth[j] = mulx2(h2, NEG1);
            ntt[j] = mulx2(t2, NEG1);
            ntm[j] = mulx2(addx2(h2, t2), NEGH);
            lofs[j] = tlabels[tj];
        }
    }

    // ---- main loop over this block's queries
    #pragma unroll
    for (int q = 0; q < QT; q++) {
        int qi = qbase + q;
        if (qi >= N) break;

        float4 qs = reinterpret_cast<const float4*>(pscrews)[qi];
        u64 qh2 = pk2(qs.x, qs.y);
        u64 qt2 = pk2(qs.z, qs.w);
        u64 qm2 = mulx2(addx2(qh2, qt2), HALF);

        if (!active) continue;

        float r[TPT];
        #pragma unroll
        for (int j = 0; j < TPT; j++) {
            u64 dm = absx2(addx2(qm2, ntm[j]));
            u64 dh = absx2(addx2(qh2, nth[j]));
            u64 dt = absx2(addx2(qt2, ntt[j]));
            u64 s2 = addx2(addx2(dm, dh), dt);
            float sx, sy;
            upk2(s2, sx, sy);
            float cls = s_cls[q * nc + lofs[j]];
            r[j] = fmaf(5.0f, sx, fmaf(5.0f, sy, cls));
        }

        long long base = (long long)qi * T + t0;
        if (full) {
            float4 v; v.x = r[0]; v.y = r[1]; v.z = r[2]; v.w = r[3];
            __stcs(reinterpret_cast<float4*>(out + base), v);
        } else {
            for (int j = 0; j < nt; j++) __stcs(out + base + j, r[j]);
        }
    }
}

extern "C" void kernel_launch(void* const* d_in, const int* in_sizes, int n_in,
                              void* d_out, int out_size) {
    const float* logits  = (const float*)d_in[0];   // [bs, nq, nc]
    const float* pscrews = (const float*)d_in[1];   // [bs, nq, 4]
    const int*   tlabels = (const int*)d_in[2];     // [T]
    const float* tscrews = (const float*)d_in[3];   // [T, 4]
    // d_in[4] (num_targets_per_image) does not affect the flat [N, T] output.

    int N  = in_sizes[1] / 4;          // bs * nq
    int nc = in_sizes[0] / N;          // 2
    int T  = in_sizes[2];              // total targets
    float* out = (float*)d_out;

    // threads: cover T with TPT targets/thread (>=256 so QT*nc fits), warp-rounded
    int need = (T + TPT - 1) / TPT;
    int tpb = need > 256 ? ((need + 31) & ~31) : 256;
    if (tpb > 1024) tpb = 1024;  // shapes beyond 4096 targets unsupported by design

    int blocks = (N + QT - 1) / QT;
    matcher_fused<<<blocks, tpb>>>(logits, pscrews, tlabels, tscrews, out, N, nc, T);
}

// round 3
// speedup vs baseline: 1.7716x; 1.0186x over previous
#include <cuda_runtime.h>
#include <cuda_bf16.h>
#include <math.h>

// HungarianMatcher cost matrix, fused single kernel (v3).
//   u = head_q - head_t,  v = tip_q - tip_t   (2-vectors, packed f32x2)
//   C = 5*(|u|_1 + |v|_1) + 2.5*|u+v|_1 + cls[label_t]
// (mid-diff = (u+v)/2 before abs, so the 0.5 folds into the 2.5 constant)
//
// Class focal costs computed once per block into smem (blocks partition
// queries), fetched as one broadcast LDS.64 per query, selected with FSEL.

#define QT 8          // queries per block
#define TPT 4         // targets per thread
#define MAXNC 16

typedef unsigned long long u64;

__device__ __forceinline__ u64 pk2(float lo, float hi) {
    u64 r; asm("mov.b64 %0, {%1, %2};" : "=l"(r) : "f"(lo), "f"(hi)); return r;
}
__device__ __forceinline__ void upk2(u64 v, float& lo, float& hi) {
    asm("mov.b64 {%0, %1}, %2;" : "=f"(lo), "=f"(hi) : "l"(v));
}
__device__ __forceinline__ u64 addx2(u64 a, u64 b) {
    u64 r; asm("add.rn.f32x2 %0, %1, %2;" : "=l"(r) : "l"(a), "l"(b)); return r;
}
__device__ __forceinline__ u64 mulx2(u64 a, u64 b) {
    u64 r; asm("mul.rn.f32x2 %0, %1, %2;" : "=l"(r) : "l"(a), "l"(b)); return r;
}
__device__ __forceinline__ u64 absx2(u64 a) {
    u64 r; asm("and.b64 %0, %1, 0x7FFFFFFF7FFFFFFF;" : "=l"(r) : "l"(a)); return r;
}

__global__ __launch_bounds__(256)
void matcher_fused(const float* __restrict__ logits,
                   const float* __restrict__ pscrews,
                   const int*   __restrict__ tlabels,
                   const float* __restrict__ tscrews,
                   float* __restrict__ out,
                   int N, int nc, int T) {
    __shared__ float s_cls[QT * MAXNC];

    int qbase = blockIdx.x * QT;

    // ---- per-block focal class costs
    int k = threadIdx.x;
    if (k < QT * nc) {
        int q = qbase + k / nc;
        int c = k % nc;
        float cost = 0.0f;
        if (q < N) {
            float l = logits[(long long)q * nc + c];
            float p = 1.0f / (1.0f + expf(-l));
            float pos = (1.0f - p) * (1.0f - p) * (-logf(p + 1e-8f));
            float neg = p * p * (-log1pf(-(p - 1e-8f)));
            cost = 2.0f * (pos - neg);
        }
        s_cls[k] = cost;
    }
    __syncthreads();

    // ---- load TPT targets into registers (negated heads/tips only)
    const u64 NEG1 = 0xBF800000BF800000ULL;  // {-1, -1}

    int t0 = threadIdx.x * TPT;
    bool active = (t0 < T);
    int nt = active ? min(TPT, T - t0) : 0;
    bool full = (nt == TPT);

    u64 nth[TPT], ntt[TPT];
    bool lsel[TPT];
    if (active) {
        #pragma unroll
        for (int j = 0; j < TPT; j++) {
            int tj = t0 + ((j < nt) ? j : (nt - 1));
            float4 s = reinterpret_cast<const float4*>(tscrews)[tj];
            nth[j] = mulx2(pk2(s.x, s.y), NEG1);
            ntt[j] = mulx2(pk2(s.z, s.w), NEG1);
            lsel[j] = (tlabels[tj] != 0);
        }
    }

    // ---- main loop over this block's queries
    #pragma unroll
    for (int q = 0; q < QT; q++) {
        int qi = qbase + q;
        if (qi >= N) break;

        float4 qs = reinterpret_cast<const float4*>(pscrews)[qi];
        u64 qh2 = pk2(qs.x, qs.y);
        u64 qt2 = pk2(qs.z, qs.w);

        if (!active) continue;

        // broadcast LDS.64: both class costs for this query (nc==2 fast path)
        float c0 = s_cls[q * nc + 0];
        float c1 = (nc > 1) ? s_cls[q * nc + 1] : c0;

        float r[TPT];
        #pragma unroll
        for (int j = 0; j < TPT; j++) {
            u64 u = addx2(qh2, nth[j]);       // head diff (signed)
            u64 v = addx2(qt2, ntt[j]);       // tip diff (signed)
            u64 w = absx2(addx2(u, v));       // |u+v| (mid*2)
            u64 s2 = addx2(absx2(u), absx2(v));
            float sx, sy, wx, wy;
            upk2(s2, sx, sy);
            upk2(w, wx, wy);
            float cls = lsel[j] ? c1 : c0;
            r[j] = fmaf(5.0f, sx,
                   fmaf(5.0f, sy,
                   fmaf(2.5f, wx,
                   fmaf(2.5f, wy, cls))));
        }

        long long base = (long long)qi * T + t0;
        if (full) {
            float4 vv; vv.x = r[0]; vv.y = r[1]; vv.z = r[2]; vv.w = r[3];
            __stcs(reinterpret_cast<float4*>(out + base), vv);
        } else {
            for (int j = 0; j < nt; j++) __stcs(out + base + j, r[j]);
        }
    }
}

extern "C" void kernel_launch(void* const* d_in, const int* in_sizes, int n_in,
                              void* d_out, int out_size) {
    const float* logits  = (const float*)d_in[0];   // [bs, nq, nc]
    const float* pscrews = (const float*)d_in[1];   // [bs, nq, 4]
    const int*   tlabels = (const int*)d_in[2];     // [T]
    const float* tscrews = (const float*)d_in[3];   // [T, 4]
    // d_in[4] (num_targets_per_image) does not affect the flat [N, T] output.

    int N  = in_sizes[1] / 4;          // bs * nq
    int nc = in_sizes[0] / N;          // 2
    int T  = in_sizes[2];              // total targets
    float* out = (float*)d_out;

    int need = (T + TPT - 1) / TPT;
    int tpb = need > 256 ? ((need + 31) & ~31) : 256;
    if (tpb > 1024) tpb = 1024;

    int blocks = (N + QT - 1) / QT;
    matcher_fused<<<blocks, tpb>>>(logits, pscrews, tlabels, tscrews, out, N, nc, T);
}

// round 4
// speedup vs baseline: 2.3078x; 1.3027x over previous
#include <cuda_runtime.h>
#include <cuda_bf16.h>
#include <math.h>

// HungarianMatcher cost matrix, fused single kernel (v4).
//   u = head_q - head_t,  v = tip_q - tip_t   (packed f32x2 diffs)
//   C = 5*(|ux|+|uy|+|vx|+|vy|) + 2.5*(|wx|+|wy|) + cls[label_t],  w = u+v
// Diffs use packed FADD2; the abs-sums are scalar FADDs so ptxas folds
// fabsf into |Ra| operand modifiers (no LOP3s). Queries staged in smem.

#define QT 8          // queries per block
#define TPT 4         // targets per thread
#define MAXNC 16

typedef unsigned long long u64;

__device__ __forceinline__ u64 pk2(float lo, float hi) {
    u64 r; asm("mov.b64 %0, {%1, %2};" : "=l"(r) : "f"(lo), "f"(hi)); return r;
}
__device__ __forceinline__ void upk2(u64 v, float& lo, float& hi) {
    asm("mov.b64 {%0, %1}, %2;" : "=f"(lo), "=f"(hi) : "l"(v));
}
__device__ __forceinline__ u64 addx2(u64 a, u64 b) {
    u64 r; asm("add.rn.f32x2 %0, %1, %2;" : "=l"(r) : "l"(a), "l"(b)); return r;
}
__device__ __forceinline__ u64 mulx2(u64 a, u64 b) {
    u64 r; asm("mul.rn.f32x2 %0, %1, %2;" : "=l"(r) : "l"(a), "l"(b)); return r;
}

__global__ __launch_bounds__(256)
void matcher_fused(const float* __restrict__ logits,
                   const float* __restrict__ pscrews,
                   const int*   __restrict__ tlabels,
                   const float* __restrict__ tscrews,
                   float* __restrict__ out,
                   int N, int nc, int T) {
    __shared__ float s_cls[QT * MAXNC];
    __shared__ float s_q[QT * 4];

    int qbase = blockIdx.x * QT;
    int k = threadIdx.x;

    // ---- stage this block's query screws (one 128B load per block)
    if (k < QT * 4) {
        int q = qbase + k / 4;
        s_q[k] = (q < N) ? pscrews[(long long)q * 4 + (k & 3)] : 0.0f;
    }

    // ---- per-block focal class costs
    if (k >= 32 && k < 32 + QT * nc) {
        int kk = k - 32;
        int q = qbase + kk / nc;
        int c = kk % nc;
        float cost = 0.0f;
        if (q < N) {
            float l = logits[(long long)q * nc + c];
            float p = 1.0f / (1.0f + expf(-l));
            float pos = (1.0f - p) * (1.0f - p) * (-logf(p + 1e-8f));
            float neg = p * p * (-log1pf(-(p - 1e-8f)));
            cost = 2.0f * (pos - neg);
        }
        s_cls[kk] = cost;
    }

    // ---- load TPT targets into registers (negated) while smem fills
    const u64 NEG1 = 0xBF800000BF800000ULL;  // {-1, -1}

    int t0 = threadIdx.x * TPT;
    bool active = (t0 < T);
    int nt = active ? min(TPT, T - t0) : 0;
    bool full = (nt == TPT);

    u64 nth[TPT], ntt[TPT];
    bool lsel[TPT];
    if (active) {
        #pragma unroll
        for (int j = 0; j < TPT; j++) {
            int tj = t0 + ((j < nt) ? j : (nt - 1));
            float4 s = reinterpret_cast<const float4*>(tscrews)[tj];
            nth[j] = mulx2(pk2(s.x, s.y), NEG1);
            ntt[j] = mulx2(pk2(s.z, s.w), NEG1);
            lsel[j] = (tlabels[tj] != 0);
        }
    }
    __syncthreads();

    // ---- main loop over this block's queries
    #pragma unroll
    for (int q = 0; q < QT; q++) {
        int qi = qbase + q;
        if (qi >= N) break;

        float4 qs = reinterpret_cast<const float4*>(s_q)[q];   // LDS.128 bcast
        u64 qh2 = pk2(qs.x, qs.y);
        u64 qt2 = pk2(qs.z, qs.w);

        if (!active) continue;

        float c0 = s_cls[q * nc + 0];
        float c1 = (nc > 1) ? s_cls[q * nc + 1] : c0;

        float r[TPT];
        #pragma unroll
        for (int j = 0; j < TPT; j++) {
            u64 u = addx2(qh2, nth[j]);      // head diff
            u64 v = addx2(qt2, ntt[j]);      // tip diff
            u64 w = addx2(u, v);             // 2*mid diff
            float ux, uy, vx, vy, wx, wy;
            upk2(u, ux, uy); upk2(v, vx, vy); upk2(w, wx, wy);
            float s1 = fabsf(ux) + fabsf(uy);    // FADD |a|,|b|
            float s2 = fabsf(vx) + fabsf(vy);
            float s3 = fabsf(wx) + fabsf(wy);
            float cls = lsel[j] ? c1 : c0;
            r[j] = fmaf(5.0f, s1 + s2, fmaf(2.5f, s3, cls));
        }

        long long base = (long long)qi * T + t0;
        if (full) {
            float4 vv; vv.x = r[0]; vv.y = r[1]; vv.z = r[2]; vv.w = r[3];
            __stcs(reinterpret_cast<float4*>(out + base), vv);
        } else {
            for (int j = 0; j < nt; j++) __stcs(out + base + j, r[j]);
        }
    }
}

extern "C" void kernel_launch(void* const* d_in, const int* in_sizes, int n_in,
                              void* d_out, int out_size) {
    const float* logits  = (const float*)d_in[0];   // [bs, nq, nc]
    const float* pscrews = (const float*)d_in[1];   // [bs, nq, 4]
    const int*   tlabels = (const int*)d_in[2];     // [T]
    const float* tscrews = (const float*)d_in[3];   // [T, 4]
    // d_in[4] (num_targets_per_image) does not affect the flat [N, T] output.

    int N  = in_sizes[1] / 4;          // bs * nq
    int nc = in_sizes[0] / N;          // 2
    int T  = in_sizes[2];              // total targets
    float* out = (float*)d_out;

    int need = (T + TPT - 1) / TPT;
    int tpb = need > 256 ? ((need + 31) & ~31) : 256;
    if (tpb > 1024) tpb = 1024;

    int blocks = (N + QT - 1) / QT;
    matcher_fused<<<blocks, tpb>>>(logits, pscrews, tlabels, tscrews, out, N, nc, T);
}

// round 5
// speedup vs baseline: 2.3468x; 1.0169x over previous
#include <cuda_runtime.h>
#include <cuda_bf16.h>
#include <math.h>

// HungarianMatcher cost matrix, fused single kernel (v5).
//   u = head_q - head_t,  v = tip_q - tip_t   (packed f32x2 diffs)
//   C = 5*(|ux|+|uy|+|vx|+|vy|) + 2.5*(|wx|+|wy|) + cls[label_t],  w = u+v
//
// v5: zero tail predication. Every thread claims t0 = min(tid*TPT, T-TPT);
// threads past the end redundantly compute/store IDENTICAL values to the
// same addresses (deterministic). Unconditional STG.128, incremental store
// pointer. Compute core unchanged from v4 (abs folded into FADD modifiers).

#define QT 8          // queries per block
#define TPT 4         // targets per thread
#define MAXNC 16

typedef unsigned long long u64;

__device__ __forceinline__ u64 pk2(float lo, float hi) {
    u64 r; asm("mov.b64 %0, {%1, %2};" : "=l"(r) : "f"(lo), "f"(hi)); return r;
}
__device__ __forceinline__ void upk2(u64 v, float& lo, float& hi) {
    asm("mov.b64 {%0, %1}, %2;" : "=f"(lo), "=f"(hi) : "l"(v));
}
__device__ __forceinline__ u64 addx2(u64 a, u64 b) {
    u64 r; asm("add.rn.f32x2 %0, %1, %2;" : "=l"(r) : "l"(a), "l"(b)); return r;
}
__device__ __forceinline__ u64 mulx2(u64 a, u64 b) {
    u64 r; asm("mul.rn.f32x2 %0, %1, %2;" : "=l"(r) : "l"(a), "l"(b)); return r;
}

__global__ __launch_bounds__(256)
void matcher_fused(const float* __restrict__ logits,
                   const float* __restrict__ pscrews,
                   const int*   __restrict__ tlabels,
                   const float* __restrict__ tscrews,
                   float* __restrict__ out,
                   int N, int nc, int T) {
    __shared__ float s_cls[QT * MAXNC];
    __shared__ float s_q[QT * 4];

    int qbase = blockIdx.x * QT;
    int k = threadIdx.x;

    // ---- stage this block's query screws (one 128B load per block)
    if (k < QT * 4) {
        int q = qbase + (k >> 2);
        s_q[k] = (q < N) ? pscrews[(long long)q * 4 + (k & 3)] : 0.0f;
    }

    // ---- per-block focal class costs
    if (k >= 32 && k < 32 + QT * nc) {
        int kk = k - 32;
        int q = qbase + kk / nc;
        int c = kk % nc;
        float cost = 0.0f;
        if (q < N) {
            float l = logits[(long long)q * nc + c];
            float p = 1.0f / (1.0f + expf(-l));
            float pos = (1.0f - p) * (1.0f - p) * (-logf(p + 1e-8f));
            float neg = p * p * (-log1pf(-(p - 1e-8f)));
            cost = 2.0f * (pos - neg);
        }
        s_cls[kk] = cost;
    }

    // ---- load TPT targets into registers (negated) while smem fills.
    // Clamp: threads past the end mirror the last full tile (identical
    // redundant work + identical stores -> deterministic, no predication).
    const u64 NEG1 = 0xBF800000BF800000ULL;  // {-1, -1}

    int t0 = threadIdx.x * TPT;
    if (t0 > T - TPT) t0 = T - TPT;          // requires T >= TPT

    u64 nth[TPT], ntt[TPT];
    bool lsel[TPT];
    #pragma unroll
    for (int j = 0; j < TPT; j++) {
        int tj = t0 + j;
        float4 s = reinterpret_cast<const float4*>(tscrews)[tj];
        nth[j] = mulx2(pk2(s.x, s.y), NEG1);
        ntt[j] = mulx2(pk2(s.z, s.w), NEG1);
        lsel[j] = (tlabels[tj] != 0);
    }
    __syncthreads();

    int qmax = N - qbase;                     // >=1; usually QT
    float* ptr = out + (long long)qbase * T + t0;

    #pragma unroll
    for (int q = 0; q < QT; q++) {
        if (q >= qmax) break;

        float4 qs = reinterpret_cast<const float4*>(s_q)[q];   // LDS.128 bcast
        u64 qh2 = pk2(qs.x, qs.y);
        u64 qt2 = pk2(qs.z, qs.w);

        float c0 = s_cls[q * nc + 0];
        float c1 = (nc > 1) ? s_cls[q * nc + 1] : c0;

        float r[TPT];
        #pragma unroll
        for (int j = 0; j < TPT; j++) {
            u64 u = addx2(qh2, nth[j]);      // head diff
            u64 v = addx2(qt2, ntt[j]);      // tip diff
            u64 w = addx2(u, v);             // 2*mid diff
            float ux, uy, vx, vy, wx, wy;
            upk2(u, ux, uy); upk2(v, vx, vy); upk2(w, wx, wy);
            float s1 = fabsf(ux) + fabsf(uy);    // FADD |a|,|b|
            float s2 = fabsf(vx) + fabsf(vy);
            float s3 = fabsf(wx) + fabsf(wy);
            float cls = lsel[j] ? c1 : c0;
            r[j] = fmaf(5.0f, s1 + s2, fmaf(2.5f, s3, cls));
        }

        float4 vv; vv.x = r[0]; vv.y = r[1]; vv.z = r[2]; vv.w = r[3];
        __stcs(reinterpret_cast<float4*>(ptr), vv);
        ptr += T;                             // incremental addressing
    }
}

extern "C" void kernel_launch(void* const* d_in, const int* in_sizes, int n_in,
                              void* d_out, int out_size) {
    const float* logits  = (const float*)d_in[0];   // [bs, nq, nc]
    const float* pscrews = (const float*)d_in[1];   // [bs, nq, 4]
    const int*   tlabels = (const int*)d_in[2];     // [T]
    const float* tscrews = (const float*)d_in[3];   // [T, 4]
    // d_in[4] (num_targets_per_image) does not affect the flat [N, T] output.

    int N  = in_sizes[1] / 4;          // bs * nq
    int nc = in_sizes[0] / N;          // 2
    int T  = in_sizes[2];              // total targets
    float* out = (float*)d_out;

    int need = (T + TPT - 1) / TPT;    // threads needed to cover T
    int tpb = need > 256 ? ((need + 31) & ~31) : 256;
    if (tpb > 1024) tpb = 1024;

    int blocks = (N + QT - 1) / QT;
    matcher_fused<<<blocks, tpb>>>(logits, pscrews, tlabels, tscrews, out, N, nc, T);
}